// round 2
// baseline (speedup 1.0000x reference)
#include <cuda_runtime.h>

#define NTH 256

namespace {
constexpr int Btok = 16384;
constexpr int TM   = 64;          // tokens per CTA
constexpr int NCTA = Btok / TM;   // 256

// shared memory layout (float offsets)
constexpr int OFF_X    = 0;       // x  [256][64]
constexpr int OFF_H256 = 16384;   // h  [256][64]
constexpr int OFF_H128 = 32768;   // h  [128][64]
constexpr int OFF_H64  = 40960;   // h  [ 64][64]
constexpr int OFF_W    = 45056;   // weight staging: 8192 floats
constexpr int OFF_G    = 53248;   // gates [64][32]
constexpr int SMEM_FLOATS = 55296;
constexpr int SMEM_BYTES  = SMEM_FLOATS * 4;   // 221184 B  (< 227 KB limit)
}

// One GEMM stage: sOut[N][64] = act( sIn[K][64]^T @ gW[K][N] + gB ), transposed layouts.
// Weights streamed through sW in chunks of KC rows (KC*N == 8192 floats always).
template<int K, int N, bool RELU>
__device__ __forceinline__ void gemm_stage(
    const float* __restrict__ sIn,
    float*       __restrict__ sOut,
    const float* __restrict__ gW,
    const float* __restrict__ gB,
    float*       __restrict__ sW,
    int tx, int ty, int tid)
{
    constexpr int NG  = N / 64;       // float4 column groups per thread
    constexpr int KC  = 8192 / N;     // k-rows per chunk
    constexpr int NCH = K / KC;
    static_assert(NG >= 1 && KC * NCH == K, "tiling mismatch");

    float acc[NG][4][4];
    #pragma unroll
    for (int g = 0; g < NG; ++g)
        #pragma unroll
        for (int t = 0; t < 4; ++t)
            #pragma unroll
            for (int c = 0; c < 4; ++c) acc[g][t][c] = 0.f;

    for (int ch = 0; ch < NCH; ++ch) {
        __syncthreads();   // everyone done reading previous sW contents
        {
            const float4* src = reinterpret_cast<const float4*>(gW + ch * KC * N);
            float4*       dst = reinterpret_cast<float4*>(sW);
            #pragma unroll
            for (int i = 0; i < 8; ++i) dst[tid + i * NTH] = src[tid + i * NTH];
        }
        __syncthreads();
        const float* sInC = sIn + ch * KC * TM;
        #pragma unroll 4
        for (int k = 0; k < KC; ++k) {
            float4 a = *reinterpret_cast<const float4*>(sInC + k * TM + 4 * tx);
            float av[4] = {a.x, a.y, a.z, a.w};
            #pragma unroll
            for (int g = 0; g < NG; ++g) {
                float4 w = *reinterpret_cast<const float4*>(sW + k * N + 64 * g + 4 * ty);
                float wv[4] = {w.x, w.y, w.z, w.w};
                #pragma unroll
                for (int t = 0; t < 4; ++t)
                    #pragma unroll
                    for (int c = 0; c < 4; ++c)
                        acc[g][t][c] += av[t] * wv[c];
            }
        }
    }

    // epilogue: bias + relu, write transposed [col][tok]
    #pragma unroll
    for (int g = 0; g < NG; ++g) {
        const int colb = 64 * g + 4 * ty;
        float4 b4v = *reinterpret_cast<const float4*>(gB + colb);
        float bv[4] = {b4v.x, b4v.y, b4v.z, b4v.w};
        #pragma unroll
        for (int c = 0; c < 4; ++c) {
            float v0 = acc[g][0][c] + bv[c];
            float v1 = acc[g][1][c] + bv[c];
            float v2 = acc[g][2][c] + bv[c];
            float v3 = acc[g][3][c] + bv[c];
            if (RELU) {
                v0 = fmaxf(v0, 0.f); v1 = fmaxf(v1, 0.f);
                v2 = fmaxf(v2, 0.f); v3 = fmaxf(v3, 0.f);
            }
            float4 v; v.x = v0; v.y = v1; v.z = v2; v.w = v3;
            *reinterpret_cast<float4*>(sOut + (colb + c) * TM + 4 * tx) = v;
        }
    }
}

__global__ void __launch_bounds__(NTH, 1) moe_dense_kernel(
    const float* __restrict__ x,
    const float* __restrict__ Wg, const float* __restrict__ bg,
    const float* __restrict__ W1, const float* __restrict__ b1,
    const float* __restrict__ W2, const float* __restrict__ b2,
    const float* __restrict__ W3, const float* __restrict__ b3,
    const float* __restrict__ W4, const float* __restrict__ b4,
    const float* __restrict__ W5, const float* __restrict__ b5,
    float* __restrict__ out)
{
    extern __shared__ float sm[];
    float* sX    = sm + OFF_X;
    float* sH256 = sm + OFF_H256;
    float* sH128 = sm + OFF_H128;
    float* sH64  = sm + OFF_H64;
    float* sW    = sm + OFF_W;
    float* sG    = sm + OFF_G;

    const int tid = threadIdx.x;
    const int tx  = tid & 15;     // token group (4 tokens)
    const int ty  = tid >> 4;     // column group
    const int b0  = blockIdx.x * TM;

    // ---- load x tile, transposed to [k][tok] ----
    #pragma unroll
    for (int i = 0; i < 16; ++i) {
        int fidx = tid + i * NTH;         // float4 index over [tok][kq]
        int tok  = fidx & 63;
        int kq   = fidx >> 6;             // 0..63
        float4 v = *reinterpret_cast<const float4*>(x + (size_t)(b0 + tok) * 256 + 4 * kq);
        sX[(4 * kq + 0) * TM + tok] = v.x;
        sX[(4 * kq + 1) * TM + tok] = v.y;
        sX[(4 * kq + 2) * TM + tok] = v.z;
        sX[(4 * kq + 3) * TM + tok] = v.w;
    }
    __syncthreads();

    // ---- gating logits: [64 tok] x [32 experts] ----
    {
        const float4* src = reinterpret_cast<const float4*>(Wg);   // 256x32 = 8192 floats
        float4*       dst = reinterpret_cast<float4*>(sW);
        #pragma unroll
        for (int i = 0; i < 8; ++i) dst[tid + i * NTH] = src[tid + i * NTH];
    }
    __syncthreads();
    {
        int tok = tid & 63;
        int eg  = (tid >> 6) * 8;
        float lg[8];
        #pragma unroll
        for (int j = 0; j < 8; ++j) lg[j] = 0.f;
        #pragma unroll 4
        for (int k = 0; k < 256; ++k) {
            float a = sX[k * TM + tok];
            float4 w0 = *reinterpret_cast<const float4*>(sW + k * 32 + eg);
            float4 w1 = *reinterpret_cast<const float4*>(sW + k * 32 + eg + 4);
            lg[0] += a * w0.x; lg[1] += a * w0.y; lg[2] += a * w0.z; lg[3] += a * w0.w;
            lg[4] += a * w1.x; lg[5] += a * w1.y; lg[6] += a * w1.z; lg[7] += a * w1.w;
        }
        #pragma unroll
        for (int j = 0; j < 8; ++j) sG[tok * 32 + eg + j] = lg[j] + bg[eg + j];
    }
    __syncthreads();
    // softmax per token (one thread per token)
    if (tid < TM) {
        float m = -1e30f;
        #pragma unroll
        for (int e2 = 0; e2 < 32; ++e2) m = fmaxf(m, sG[tid * 32 + e2]);
        float s = 0.f;
        #pragma unroll
        for (int e2 = 0; e2 < 32; ++e2) {
            float v = expf(sG[tid * 32 + e2] - m);
            sG[tid * 32 + e2] = v;
            s += v;
        }
        float inv = 1.f / s;
        #pragma unroll
        for (int e2 = 0; e2 < 32; ++e2) sG[tid * 32 + e2] *= inv;
    }
    __syncthreads();

    // ---- expert loop with fused output accumulation ----
    float oacc[2][4][4];
    #pragma unroll
    for (int g = 0; g < 2; ++g)
        #pragma unroll
        for (int t = 0; t < 4; ++t)
            #pragma unroll
            for (int c = 0; c < 4; ++c) oacc[g][t][c] = 0.f;

    for (int e = 0; e < 32; ++e) {
        gemm_stage<256,  64, true>(sX,    sH64,  W1 + e * 256 * 64,  b1 + e * 64,  sW, tx, ty, tid);
        gemm_stage< 64, 256, true>(sH64,  sH256, W2 + e * 64 * 256,  b2 + e * 256, sW, tx, ty, tid);
        gemm_stage<256, 128, true>(sH256, sH128, W3 + e * 256 * 128, b3 + e * 128, sW, tx, ty, tid);
        gemm_stage<128,  64, true>(sH128, sH64,  W4 + e * 128 * 64,  b4 + e * 64,  sW, tx, ty, tid);

        // ---- stage 5 fused with gated accumulation (K=64, N=128, no relu) ----
        __syncthreads();
        {
            const float4* src = reinterpret_cast<const float4*>(W5 + e * 64 * 128);
            float4*       dst = reinterpret_cast<float4*>(sW);
            #pragma unroll
            for (int i = 0; i < 8; ++i) dst[tid + i * NTH] = src[tid + i * NTH];
        }
        __syncthreads();
        float y[2][4][4];
        #pragma unroll
        for (int g = 0; g < 2; ++g)
            #pragma unroll
            for (int t = 0; t < 4; ++t)
                #pragma unroll
                for (int c = 0; c < 4; ++c) y[g][t][c] = 0.f;
        #pragma unroll 4
        for (int k = 0; k < 64; ++k) {
            float4 a = *reinterpret_cast<const float4*>(sH64 + k * TM + 4 * tx);
            float av[4] = {a.x, a.y, a.z, a.w};
            #pragma unroll
            for (int g = 0; g < 2; ++g) {
                float4 w = *reinterpret_cast<const float4*>(sW + k * 128 + 64 * g + 4 * ty);
                float wv[4] = {w.x, w.y, w.z, w.w};
                #pragma unroll
                for (int t = 0; t < 4; ++t)
                    #pragma unroll
                    for (int c = 0; c < 4; ++c)
                        y[g][t][c] += av[t] * wv[c];
            }
        }
        float gate[4];
        #pragma unroll
        for (int t = 0; t < 4; ++t) gate[t] = sG[(4 * tx + t) * 32 + e];
        #pragma unroll
        for (int g = 0; g < 2; ++g) {
            float4 bv4 = *reinterpret_cast<const float4*>(b5 + e * 128 + 64 * g + 4 * ty);
            float bv[4] = {bv4.x, bv4.y, bv4.z, bv4.w};
            #pragma unroll
            for (int t = 0; t < 4; ++t)
                #pragma unroll
                for (int c = 0; c < 4; ++c)
                    oacc[g][t][c] += gate[t] * (y[g][t][c] + bv[c]);
        }
    }

    // ---- write output [64 tok][128] ----
    #pragma unroll
    for (int g = 0; g < 2; ++g)
        #pragma unroll
        for (int t = 0; t < 4; ++t) {
            float4 v;
            v.x = oacc[g][t][0]; v.y = oacc[g][t][1];
            v.z = oacc[g][t][2]; v.w = oacc[g][t][3];
            *reinterpret_cast<float4*>(out + (size_t)(b0 + 4 * tx + t) * 128 + 64 * g + 4 * ty) = v;
        }
}

extern "C" void kernel_launch(void* const* d_in, const int* in_sizes, int n_in,
                              void* d_out, int out_size)
{
    (void)in_sizes; (void)n_in; (void)out_size;
    const float* x  = (const float*)d_in[0];
    const float* Wg = (const float*)d_in[1];
    const float* bg = (const float*)d_in[2];
    const float* W1 = (const float*)d_in[3];
    const float* b1 = (const float*)d_in[4];
    const float* W2 = (const float*)d_in[5];
    const float* b2 = (const float*)d_in[6];
    const float* W3 = (const float*)d_in[7];
    const float* b3 = (const float*)d_in[8];
    const float* W4 = (const float*)d_in[9];
    const float* b4 = (const float*)d_in[10];
    const float* W5 = (const float*)d_in[11];
    const float* b5 = (const float*)d_in[12];
    float* out = (float*)d_out;

    cudaFuncSetAttribute(moe_dense_kernel,
                         cudaFuncAttributeMaxDynamicSharedMemorySize, SMEM_BYTES);
    moe_dense_kernel<<<NCTA, NTH, SMEM_BYTES>>>(
        x, Wg, bg, W1, b1, W2, b2, W3, b3, W4, b4, W5, b5, out);
}

// round 4
// speedup vs baseline: 3.2603x; 3.2603x over previous
#include <cuda_runtime.h>
#include <cstdint>

#define NTH 256

namespace {
constexpr int E    = 32;
constexpr int TOK  = 64;
constexpr int NCTA = 16384 / TOK;   // 256

// repacked weight offsets (floats, per expert)
constexpr int OFW1  = 0;        // K=256,N=64  : 16384
constexpr int OFW2A = 16384;    // K=64, N=128 : 8192
constexpr int OFW2B = 24576;    // K=64, N=128 : 8192
constexpr int OFW3  = 32768;    // K=256,N=128 : 32768
constexpr int OFW4  = 65536;    // K=128,N=64  : 8192
constexpr int OFW5  = 73728;    // K=64, N=128 : 8192
constexpr int EXPSTRIDE = 81920;

// smem float offsets
constexpr int OFF_X   = 0;       // x tf32, fragment-pair layout, stride 264 -> 16896
constexpr int OFF_H2  = 16896;   // h2 (stride 264) / fp32 x copy (stride 260) -> 16896
constexpr int OFF_H3  = 33792;   // h3 stride 136 -> 8704 (also logits tmp)
constexpr int OFF_H64 = 42496;   // h1/h4 stride 72 -> 4608
constexpr int OFF_W   = 47104;   // weight double buffer 2 x 4096 floats
constexpr int OFF_G   = 55296;   // gates [E][64] -> 2048
constexpr int SMEM_FLOATS = 57344;
constexpr int SMEM_BYTES  = SMEM_FLOATS * 4;   // 229376

constexpr int STR_X  = 264;   // K=256 stages
constexpr int STR_H2 = 264;
constexpr int STR_H3 = 136;   // K=128
constexpr int STR_H64 = 72;   // K=64

__device__ float g_Wt[E * EXPSTRIDE];   // 10.5 MB repacked tf32 weights
}

// ---------------- PTX helpers ----------------
__device__ __forceinline__ uint32_t smem_u32(const void* p) {
    uint32_t a;
    asm("{ .reg .u64 t; cvta.to.shared.u64 t, %1; cvt.u32.u64 %0, t; }" : "=r"(a) : "l"(p));
    return a;
}
__device__ __forceinline__ uint32_t f2tf32(float f) {
    uint32_t r;
    asm("cvt.rna.tf32.f32 %0, %1;" : "=r"(r) : "f"(f));
    return r;
}
__device__ __forceinline__ float tfv(float f) { return __uint_as_float(f2tf32(f)); }

__device__ __forceinline__ void mma8(float* d, const uint32_t* a, uint32_t b0, uint32_t b1) {
    asm volatile("mma.sync.aligned.m16n8k8.row.col.f32.tf32.tf32.f32 "
        "{%0,%1,%2,%3}, {%4,%5,%6,%7}, {%8,%9}, {%0,%1,%2,%3};"
        : "+f"(d[0]), "+f"(d[1]), "+f"(d[2]), "+f"(d[3])
        : "r"(a[0]), "r"(a[1]), "r"(a[2]), "r"(a[3]), "r"(b0), "r"(b1));
}

__device__ __forceinline__ void prefetch_chunk(uint32_t smW, int buf, const float* src, int tid) {
    uint32_t dst = smW + (uint32_t)buf * 16384u + (uint32_t)tid * 16u;
    const char* s = reinterpret_cast<const char*>(src) + tid * 16;
    #pragma unroll
    for (int i = 0; i < 4; ++i)
        asm volatile("cp.async.cg.shared.global [%0], [%1], 16;"
                     :: "r"(dst + i * 4096u), "l"(s + i * 4096) : "memory");
}
#define CP_COMMIT() asm volatile("cp.async.commit_group;" ::: "memory")
#define CP_WAIT0()  asm volatile("cp.async.wait_group 0;" ::: "memory")

// ---------------- weight repack ----------------
// Source W[e][k][n] row-major -> fragment-ordered tf32 blocks of Nblk columns.
template<int K, int NSRC, int NBLK, int SBASE>
__global__ void repack_kernel(const float* __restrict__ W) {
    int idx = blockIdx.x * blockDim.x + threadIdx.x;
    if (idx >= E * K * NSRC) return;
    int e = idx / (K * NSRC), r = idx % (K * NSRC);
    int k = r / NSRC, n = r % NSRC;
    int blk = n / NBLK, nl = n % NBLK;
    int dst = e * EXPSTRIDE + SBASE + blk * (K * NBLK)
            + (((k >> 3) * (NBLK / 8) + (nl >> 3)) * 32 + (nl & 7) * 4 + (k & 3)) * 2
            + ((k >> 2) & 1);
    g_Wt[dst] = tfv(W[idx]);
}

// ---------------- fused stage ----------------
// D[64, NBLK] = A[64, K] @ B' + bias, relu or gated-accumulate.
template<int K, int NBLK, bool GATED>
__device__ __forceinline__ void run_stage(
    float* sm, uint32_t smW, int& pbuf,
    const float* __restrict__ gB, const float* __restrict__ gBnext,
    const float* __restrict__ bias,
    const float* __restrict__ sA, int strideA,
    float* __restrict__ sOut, int strideOut,
    float* oacc, const float* __restrict__ gate_col,
    int tid)
{
    constexpr int NT  = NBLK / 32;       // n8 tiles per warp
    constexpr int KPC = 512 / NBLK;      // ksteps per 16KB chunk
    constexpr int NCH = (K / 8) / KPC;
    const int lane = tid & 31, wid = tid >> 5;
    const int wm = wid & 1, wn = wid >> 1;
    const int ri = lane >> 2, c = lane & 3;
    const int mbase = wm * 32;
    const float* sWf = sm + OFF_W;

    float d[2][NT][4];
    #pragma unroll
    for (int mt = 0; mt < 2; ++mt)
        #pragma unroll
        for (int t8 = 0; t8 < NT; ++t8)
            #pragma unroll
            for (int q = 0; q < 4; ++q) d[mt][t8][q] = 0.f;

    for (int ch = 0; ch < NCH; ++ch) {
        CP_WAIT0();
        __syncthreads();
        const float* nxt = (ch + 1 < NCH) ? (gB + (ch + 1) * 4096) : gBnext;
        prefetch_chunk(smW, pbuf ^ 1, nxt, tid);
        CP_COMMIT();
        const float* B = sWf + pbuf * 4096;
        #pragma unroll
        for (int ksl = 0; ksl < KPC; ++ksl) {
            const int ks = ch * KPC + ksl;
            uint32_t a[2][4];
            #pragma unroll
            for (int mt = 0; mt < 2; ++mt) {
                const float* ar = sA + (mbase + mt * 16 + ri) * strideA + ks * 8 + c * 2;
                float2 lo = *reinterpret_cast<const float2*>(ar);
                float2 hi = *reinterpret_cast<const float2*>(ar + 8 * strideA);
                a[mt][0] = __float_as_uint(lo.x); a[mt][1] = __float_as_uint(hi.x);
                a[mt][2] = __float_as_uint(lo.y); a[mt][3] = __float_as_uint(hi.y);
            }
            #pragma unroll
            for (int t8 = 0; t8 < NT; ++t8) {
                float2 bb = *reinterpret_cast<const float2*>(
                    B + ((ksl * (NBLK / 8) + wn * NT + t8) * 32 + lane) * 2);
                uint32_t b0 = __float_as_uint(bb.x), b1 = __float_as_uint(bb.y);
                mma8(d[0][t8], a[0], b0, b1);
                mma8(d[1][t8], a[1], b0, b1);
            }
        }
        pbuf ^= 1;
    }

    // epilogue
    const int posF0 = ((2 * c) & 3) * 2 + (c >> 1);
    const int posF1 = ((2 * c + 1) & 3) * 2 + ((2 * c + 1) >> 2);
    #pragma unroll
    for (int mt = 0; mt < 2; ++mt) {
        const int r0 = mbase + mt * 16 + ri;
        #pragma unroll
        for (int t8 = 0; t8 < NT; ++t8) {
            const int n0 = wn * (NT * 8) + t8 * 8 + 2 * c;
            const float bz0 = __ldg(bias + n0), bz1 = __ldg(bias + n0 + 1);
            if (GATED) {
                const float g0 = gate_col[r0], g1 = gate_col[r0 + 8];
                float* o = oacc + (mt * NT + t8) * 4;
                o[0] += g0 * (d[mt][t8][0] + bz0);
                o[1] += g0 * (d[mt][t8][1] + bz1);
                o[2] += g1 * (d[mt][t8][2] + bz0);
                o[3] += g1 * (d[mt][t8][3] + bz1);
            } else {
                const int ks_o = wn * NT + t8;
                float* o0 = sOut + r0 * strideOut + ks_o * 8;
                float* o1 = o0 + 8 * strideOut;
                o0[posF0] = tfv(fmaxf(d[mt][t8][0] + bz0, 0.f));
                o0[posF1] = tfv(fmaxf(d[mt][t8][1] + bz1, 0.f));
                o1[posF0] = tfv(fmaxf(d[mt][t8][2] + bz0, 0.f));
                o1[posF1] = tfv(fmaxf(d[mt][t8][3] + bz1, 0.f));
            }
        }
    }
}

// ---------------- main kernel ----------------
__global__ void __launch_bounds__(NTH, 1) moe_mma_kernel(
    const float* __restrict__ x,
    const float* __restrict__ Wg, const float* __restrict__ bg,
    const float* __restrict__ b1, const float* __restrict__ b2,
    const float* __restrict__ b3, const float* __restrict__ b4,
    const float* __restrict__ b5,
    float* __restrict__ out)
{
    extern __shared__ float sm[];
    float* sX   = sm + OFF_X;
    float* sH2  = sm + OFF_H2;
    float* sH3  = sm + OFF_H3;
    float* sH64 = sm + OFF_H64;
    float* sWf  = sm + OFF_W;
    float* sG   = sm + OFF_G;
    const uint32_t smW = smem_u32(sm) + OFF_W * 4;

    const int tid = threadIdx.x;
    const int b0  = blockIdx.x * TOK;

    // ---- pass 1: x -> fp32 copy (sH2, stride 260) + tf32 fragment-pair layout (sX) ----
    #pragma unroll
    for (int i = 0; i < 16; ++i) {
        int f = tid + i * NTH;
        int tok = f >> 6, kq = (f & 63) * 4;
        float4 v = *reinterpret_cast<const float4*>(x + (size_t)(b0 + tok) * 256 + kq);
        *reinterpret_cast<float4*>(sH2 + tok * 260 + kq) = v;
        int base = tok * STR_X + (kq >> 3) * 8 + ((kq >> 2) & 1);
        sX[base + 0] = tfv(v.x);
        sX[base + 2] = tfv(v.y);
        sX[base + 4] = tfv(v.z);
        sX[base + 6] = tfv(v.w);
    }
    // Wg -> weight buffer area (32KB = both buffers)
    {
        const float4* s4 = reinterpret_cast<const float4*>(Wg);
        float4* d4 = reinterpret_cast<float4*>(sWf);
        #pragma unroll
        for (int i = 0; i < 8; ++i) d4[tid + i * NTH] = s4[tid + i * NTH];
    }
    __syncthreads();

    // ---- gating logits ----
    {
        int tok = tid & 63, eg = (tid >> 6) * 8;
        float lg[8];
        #pragma unroll
        for (int j = 0; j < 8; ++j) lg[j] = 0.f;
        #pragma unroll 4
        for (int k = 0; k < 256; ++k) {
            float a = sH2[tok * 260 + k];
            float4 w0 = *reinterpret_cast<const float4*>(sWf + k * 32 + eg);
            float4 w1 = *reinterpret_cast<const float4*>(sWf + k * 32 + eg + 4);
            lg[0] += a * w0.x; lg[1] += a * w0.y; lg[2] += a * w0.z; lg[3] += a * w0.w;
            lg[4] += a * w1.x; lg[5] += a * w1.y; lg[6] += a * w1.z; lg[7] += a * w1.w;
        }
        #pragma unroll
        for (int j = 0; j < 8; ++j) sH3[tok * 32 + eg + j] = lg[j] + __ldg(bg + eg + j);
    }
    __syncthreads();
    if (tid < TOK) {
        float lv[32];
        float m = -1e30f;
        #pragma unroll
        for (int e2 = 0; e2 < 32; ++e2) { lv[e2] = sH3[tid * 32 + e2]; m = fmaxf(m, lv[e2]); }
        float s = 0.f;
        #pragma unroll
        for (int e2 = 0; e2 < 32; ++e2) { lv[e2] = expf(lv[e2] - m); s += lv[e2]; }
        float inv = 1.f / s;
        #pragma unroll
        for (int e2 = 0; e2 < 32; ++e2) sG[e2 * TOK + tid] = lv[e2] * inv;
    }
    __syncthreads();

    // ---- expert loop ----
    float oacc[32];
    #pragma unroll
    for (int j = 0; j < 32; ++j) oacc[j] = 0.f;

    int pbuf = 0;
    prefetch_chunk(smW, 0, g_Wt + OFW1, tid);   // expert 0, S1 chunk 0
    CP_COMMIT();

    for (int e = 0; e < E; ++e) {
        const float* wb  = g_Wt + (size_t)e * EXPSTRIDE;
        const float* wbn = g_Wt + (size_t)((e + 1) & 31) * EXPSTRIDE;

        run_stage<256,  64, false>(sm, smW, pbuf, wb + OFW1,  wb + OFW2A, b1 + e * 64,
                                   sX,  STR_X,  sH64, STR_H64, nullptr, nullptr, tid);
        run_stage< 64, 128, false>(sm, smW, pbuf, wb + OFW2A, wb + OFW2B, b2 + e * 256,
                                   sH64, STR_H64, sH2, STR_H2, nullptr, nullptr, tid);
        run_stage< 64, 128, false>(sm, smW, pbuf, wb + OFW2B, wb + OFW3,  b2 + e * 256 + 128,
                                   sH64, STR_H64, sH2 + 128, STR_H2, nullptr, nullptr, tid);
        run_stage<256, 128, false>(sm, smW, pbuf, wb + OFW3,  wb + OFW4,  b3 + e * 128,
                                   sH2, STR_H2, sH3, STR_H3, nullptr, nullptr, tid);
        run_stage<128,  64, false>(sm, smW, pbuf, wb + OFW4,  wb + OFW5,  b4 + e * 64,
                                   sH3, STR_H3, sH64, STR_H64, nullptr, nullptr, tid);
        run_stage< 64, 128, true >(sm, smW, pbuf, wb + OFW5,  wbn + OFW1, b5 + e * 128,
                                   sH64, STR_H64, nullptr, 0, oacc, sG + e * TOK, tid);
    }
    CP_WAIT0();

    // ---- write output [64][128] ----
    {
        const int lane = tid & 31, wid = tid >> 5;
        const int wm = wid & 1, wn = wid >> 1;
        const int ri = lane >> 2, c = lane & 3;
        #pragma unroll
        for (int mt = 0; mt < 2; ++mt) {
            int r0 = wm * 32 + mt * 16 + ri;
            #pragma unroll
            for (int t8 = 0; t8 < 4; ++t8) {
                int n0 = wn * 32 + t8 * 8 + 2 * c;
                const float* o = oacc + (mt * 4 + t8) * 4;
                float2 v0; v0.x = o[0]; v0.y = o[1];
                float2 v1; v1.x = o[2]; v1.y = o[3];
                *reinterpret_cast<float2*>(out + (size_t)(b0 + r0) * 128 + n0) = v0;
                *reinterpret_cast<float2*>(out + (size_t)(b0 + r0 + 8) * 128 + n0) = v1;
            }
        }
    }
}

// ---------------- launcher ----------------
extern "C" void kernel_launch(void* const* d_in, const int* in_sizes, int n_in,
                              void* d_out, int out_size)
{
    (void)in_sizes; (void)n_in; (void)out_size;
    const float* x  = (const float*)d_in[0];
    const float* Wg = (const float*)d_in[1];
    const float* bg = (const float*)d_in[2];
    const float* W1 = (const float*)d_in[3];
    const float* b1 = (const float*)d_in[4];
    const float* W2 = (const float*)d_in[5];
    const float* b2 = (const float*)d_in[6];
    const float* W3 = (const float*)d_in[7];
    const float* b3 = (const float*)d_in[8];
    const float* W4 = (const float*)d_in[9];
    const float* b4 = (const float*)d_in[10];
    const float* W5 = (const float*)d_in[11];
    const float* b5 = (const float*)d_in[12];
    float* out = (float*)d_out;

    repack_kernel<256,  64,  64, OFW1 ><<<(E * 16384 + 255) / 256, 256>>>(W1);
    repack_kernel< 64, 256, 128, OFW2A><<<(E * 16384 + 255) / 256, 256>>>(W2);
    repack_kernel<256, 128, 128, OFW3 ><<<(E * 32768 + 255) / 256, 256>>>(W3);
    repack_kernel<128,  64,  64, OFW4 ><<<(E *  8192 + 255) / 256, 256>>>(W4);
    repack_kernel< 64, 128, 128, OFW5 ><<<(E *  8192 + 255) / 256, 256>>>(W5);

    cudaFuncSetAttribute(moe_mma_kernel,
                         cudaFuncAttributeMaxDynamicSharedMemorySize, SMEM_BYTES);
    moe_mma_kernel<<<NCTA, NTH, SMEM_BYTES>>>(x, Wg, bg, b1, b2, b3, b4, b5, out);
}

// round 5
// speedup vs baseline: 6.3831x; 1.9578x over previous
#include <cuda_runtime.h>
#include <cuda_fp16.h>
#include <cstdint>

#define NTH 256

namespace {
constexpr int E    = 32;
constexpr int TOK  = 64;
constexpr int NCTA = 16384 / TOK;   // 256

// repacked f16 weights: per-expert 81920 halves (40960 b32), 5 chunks of 32KB
constexpr int EXP_F16   = 81920;
constexpr int TOTAL_F16 = E * EXP_F16;        // 2,621,440
constexpr int CHUNK_F16 = 16384;              // 32KB

// smem byte offsets
constexpr int OFF_SX  = 0;        // x A-frag (K=256): 32768
constexpr int OFF_H2  = 32768;    // h2 A-frag (K=256): 32768
constexpr int OFF_H3  = 65536;    // h3 A-frag (K=128): 16384 (also logits tmp)
constexpr int OFF_H64 = 81920;    // h1/h4 A-frag (K=64): 8192
constexpr int OFF_WB  = 90112;    // weight double buffer: 2 x 32768
constexpr int OFF_G   = 155648;   // gates [E][64] f32: 8192
constexpr int SMEM_BYTES = 163840;

__device__ __align__(16) __half g_Wh[TOTAL_F16];
}

// ---------------- helpers ----------------
__device__ __forceinline__ uint32_t smem_u32(const void* p) {
    uint32_t a;
    asm("{ .reg .u64 t; cvta.to.shared.u64 t, %1; cvt.u32.u64 %0, t; }" : "=r"(a) : "l"(p));
    return a;
}
__device__ __forceinline__ uint32_t packh(float lo, float hi) {
    uint32_t r;
    asm("cvt.rn.f16x2.f32 %0, %1, %2;" : "=r"(r) : "f"(hi), "f"(lo));  // d.lo = 2nd operand
    return r;
}
__device__ __forceinline__ void mma16(float* d, const uint32_t* a, uint32_t b0, uint32_t b1) {
    asm volatile("mma.sync.aligned.m16n8k16.row.col.f32.f16.f16.f32 "
        "{%0,%1,%2,%3}, {%4,%5,%6,%7}, {%8,%9}, {%0,%1,%2,%3};"
        : "+f"(d[0]), "+f"(d[1]), "+f"(d[2]), "+f"(d[3])
        : "r"(a[0]), "r"(a[1]), "r"(a[2]), "r"(a[3]), "r"(b0), "r"(b1));
}
__device__ __forceinline__ void lds128(uint32_t* r, uint32_t addr) {
    asm volatile("ld.shared.v4.u32 {%0,%1,%2,%3}, [%4];"
        : "=r"(r[0]), "=r"(r[1]), "=r"(r[2]), "=r"(r[3]) : "r"(addr));
}
__device__ __forceinline__ void sts64(uint32_t addr, uint32_t h0, uint32_t h1) {
    asm volatile("st.shared.v2.u32 [%0], {%1,%2};" :: "r"(addr), "r"(h0), "r"(h1) : "memory");
}
__device__ __forceinline__ void prefetch32k(uint32_t dst, const __half* src, int tid) {
    uint32_t d = dst + (uint32_t)tid * 16u;
    const char* s = reinterpret_cast<const char*>(src) + tid * 16;
    #pragma unroll
    for (int i = 0; i < 8; ++i)
        asm volatile("cp.async.cg.shared.global [%0], [%1], 16;"
                     :: "r"(d + i * 4096u), "l"(s + i * 4096) : "memory");
}
#define CP_COMMIT() asm volatile("cp.async.commit_group;" ::: "memory")
#define CP_WAIT0()  asm volatile("cp.async.wait_group 0;" ::: "memory")

// ---------------- merged weight repack ----------------
// W[e][k][n] row-major -> B-fragment order f16 in g_Wh.
__device__ __forceinline__ void repack_one(const float* __restrict__ W, int r,
                                           int K, int N, int base_b32) {
    int KN = K * N;
    int e = r / KN, rr = r % KN;
    int k = rr / N, n = rr % N;
    float v = W[r];
    int b32 = ((k >> 4) * (N >> 4) + (n >> 4)) * 128
            + ((n & 7) * 4 + ((k >> 1) & 3)) * 4
            + ((n >> 3) & 1) * 2 + ((k >> 3) & 1);
    g_Wh[(e * 40960 + base_b32 + b32) * 2 + (k & 1)] = __float2half_rn(v);
}

__global__ void repack_all(const float* __restrict__ W1, const float* __restrict__ W2,
                           const float* __restrict__ W3, const float* __restrict__ W4,
                           const float* __restrict__ W5) {
    int idx = blockIdx.x * blockDim.x + threadIdx.x;
    if      (idx <  524288) repack_one(W1, idx,           256,  64, 0);
    else if (idx < 1048576) repack_one(W2, idx -  524288,  64, 256, 8192);
    else if (idx < 2097152) repack_one(W3, idx - 1048576, 256, 128, 16384);
    else if (idx < 2359296) repack_one(W4, idx - 2097152, 128,  64, 32768);
    else if (idx < 2621440) repack_one(W5, idx - 2359296,  64, 128, 36864);
}

// ---------------- fused stage ----------------
// D[64, NBLK] = A_frag[64, K16TOT*16] @ B_chunks + bias; relu->frag (STS.64) or gated accumulate.
template<int K16TOT, int K16PC, int NBLK, int NT, bool GATED, bool CONSUME>
__device__ __forceinline__ void stage(
    uint32_t smA, uint32_t smOut, uint32_t smW,
    int& pbuf, int& cnext,
    const float* __restrict__ bias,
    const float* __restrict__ gate, float* oacc,
    int tid, uint32_t extraB)
{
    const int lane = tid & 31, wid = tid >> 5;
    const int wm = wid & 1, wn = wid >> 1;
    const int c = lane & 3, ri = lane >> 2;

    float d[2][NT][4];
    #pragma unroll
    for (int mt = 0; mt < 2; ++mt)
        #pragma unroll
        for (int t = 0; t < NT; ++t)
            #pragma unroll
            for (int q = 0; q < 4; ++q) d[mt][t][q] = 0.f;

    uint32_t ub = CONSUME ? (uint32_t)pbuf : (uint32_t)(pbuf ^ 1);
    if (!CONSUME) __syncthreads();   // order prior epilogue STS before our LDS

    constexpr int NCH = CONSUME ? (K16TOT / K16PC) : 1;
    #pragma unroll
    for (int ch = 0; ch < NCH; ++ch) {
        if (CONSUME) {
            CP_WAIT0();
            __syncthreads();
            int noff = cnext * CHUNK_F16;
            if (noff >= TOTAL_F16) noff = 0;
            prefetch32k(smW + (uint32_t)(pbuf ^ 1) * 32768u, g_Wh + noff, tid);
            CP_COMMIT();
            ++cnext;
            ub = (uint32_t)pbuf;
        }
        #pragma unroll
        for (int kl = 0; kl < K16PC; ++kl) {
            const int k16 = ch * K16PC + kl;
            uint32_t a[2][4];
            #pragma unroll
            for (int mt = 0; mt < 2; ++mt)
                lds128(a[mt], smA + (uint32_t)((((wm * 2 + mt) * K16TOT + k16) * 32 + lane) * 16));
            #pragma unroll
            for (int p = 0; p < NT / 2; ++p) {
                uint32_t b[4];
                uint32_t bd = smW + ub * 32768u + extraB
                    + (uint32_t)(((kl * (NBLK / 16) + wn * (NT / 2) + p) * 32 + lane) * 16);
                lds128(b, bd);
                mma16(d[0][2 * p],     a[0], b[0], b[1]);
                mma16(d[1][2 * p],     a[1], b[0], b[1]);
                mma16(d[0][2 * p + 1], a[0], b[2], b[3]);
                mma16(d[1][2 * p + 1], a[1], b[2], b[3]);
            }
        }
        if (CONSUME) pbuf ^= 1;
    }

    // epilogue
    #pragma unroll
    for (int mt = 0; mt < 2; ++mt) {
        const int r0 = wm * 32 + mt * 16 + ri;
        #pragma unroll
        for (int t8 = 0; t8 < NT; ++t8) {
            const int n0 = wn * (NT * 8) + t8 * 8 + 2 * c;
            const float bz0 = __ldg(bias + n0), bz1 = __ldg(bias + n0 + 1);
            if (GATED) {
                const float g0 = gate[r0], g1 = gate[r0 + 8];
                float* o = oacc + (mt * NT + t8) * 4;
                o[0] += g0 * (d[mt][t8][0] + bz0);
                o[1] += g0 * (d[mt][t8][1] + bz1);
                o[2] += g1 * (d[mt][t8][2] + bz0);
                o[3] += g1 * (d[mt][t8][3] + bz1);
            } else {
                constexpr int K16N = NBLK / 16;
                uint32_t h0 = packh(fmaxf(d[mt][t8][0] + bz0, 0.f),
                                    fmaxf(d[mt][t8][1] + bz1, 0.f));
                uint32_t h1 = packh(fmaxf(d[mt][t8][2] + bz0, 0.f),
                                    fmaxf(d[mt][t8][3] + bz1, 0.f));
                uint32_t dst = smOut
                    + (uint32_t)((((wm * 2 + mt) * K16N + ((wn * NT + t8) >> 1)) * 32 + lane) * 16)
                    + (uint32_t)((t8 & 1) * 8);
                sts64(dst, h0, h1);
            }
        }
    }
}

// ---------------- main kernel ----------------
__global__ void __launch_bounds__(NTH, 1) moe_f16_kernel(
    const float* __restrict__ x,
    const float* __restrict__ Wg, const float* __restrict__ bg,
    const float* __restrict__ b1, const float* __restrict__ b2,
    const float* __restrict__ b3, const float* __restrict__ b4,
    const float* __restrict__ b5,
    float* __restrict__ out)
{
    extern __shared__ char smem[];
    const uint32_t smb = smem_u32(smem);
    const uint32_t smX = smb + OFF_SX, smH2 = smb + OFF_H2;
    const uint32_t smH3 = smb + OFF_H3, smH64 = smb + OFF_H64;
    const uint32_t smW = smb + OFF_WB;
    float* sWg  = reinterpret_cast<float*>(smem + OFF_WB);
    float* sLog = reinterpret_cast<float*>(smem + OFF_H3);
    float* sG   = reinterpret_cast<float*>(smem + OFF_G);

    const int tid = threadIdx.x;
    const int b0  = blockIdx.x * TOK;

    // ---- x -> A-fragment f16 layout ----
    #pragma unroll
    for (int i = 0; i < 32; ++i) {
        int u = tid + i * NTH;            // b32 unit over 64 tok x 128 k-pairs
        int tok = u >> 7, k2 = u & 127;
        int k = 2 * k2;
        float2 v = *reinterpret_cast<const float2*>(x + (size_t)(b0 + tok) * 256 + k);
        uint32_t h = packh(v.x, v.y);
        uint32_t b32i = (uint32_t)(((tok >> 4) * 16 + (k >> 4)) * 128
                      + ((tok & 7) * 4 + ((k >> 1) & 3)) * 4
                      + ((k >> 3) & 1) * 2 + ((tok >> 3) & 1));
        *reinterpret_cast<uint32_t*>(smem + OFF_SX + b32i * 4) = h;
    }
    // Wg -> smem (f32, 32KB into weight buffer area)
    {
        const float4* s4 = reinterpret_cast<const float4*>(Wg);
        float4* d4 = reinterpret_cast<float4*>(smem + OFF_WB);
        #pragma unroll
        for (int i = 0; i < 8; ++i) d4[tid + i * NTH] = s4[tid + i * NTH];
    }
    __syncthreads();

    // ---- gating logits (fp32, x read from gmem) ----
    {
        int tok = tid & 63, eg = (tid >> 6) * 8;
        float lg[8];
        #pragma unroll
        for (int j = 0; j < 8; ++j) lg[j] = 0.f;
        const float* xr = x + (size_t)(b0 + tok) * 256;
        #pragma unroll 4
        for (int k = 0; k < 256; ++k) {
            float a = __ldg(xr + k);
            float4 w0 = *reinterpret_cast<const float4*>(sWg + k * 32 + eg);
            float4 w1 = *reinterpret_cast<const float4*>(sWg + k * 32 + eg + 4);
            lg[0] += a * w0.x; lg[1] += a * w0.y; lg[2] += a * w0.z; lg[3] += a * w0.w;
            lg[4] += a * w1.x; lg[5] += a * w1.y; lg[6] += a * w1.z; lg[7] += a * w1.w;
        }
        #pragma unroll
        for (int j = 0; j < 8; ++j) sLog[tok * 32 + eg + j] = lg[j] + __ldg(bg + eg + j);
    }
    __syncthreads();
    if (tid < TOK) {
        float lv[32];
        float m = -1e30f;
        #pragma unroll
        for (int e2 = 0; e2 < 32; ++e2) { lv[e2] = sLog[tid * 32 + e2]; m = fmaxf(m, lv[e2]); }
        float s = 0.f;
        #pragma unroll
        for (int e2 = 0; e2 < 32; ++e2) { lv[e2] = expf(lv[e2] - m); s += lv[e2]; }
        float inv = 1.f / s;
        #pragma unroll
        for (int e2 = 0; e2 < 32; ++e2) sG[e2 * TOK + tid] = lv[e2] * inv;
    }
    __syncthreads();

    // ---- expert loop ----
    float oacc[32];
    #pragma unroll
    for (int j = 0; j < 32; ++j) oacc[j] = 0.f;

    int pbuf = 0, cnext = 1;
    prefetch32k(smW, g_Wh, tid);   // expert 0, chunk 0 (S1)
    CP_COMMIT();

    for (int e = 0; e < E; ++e) {
        // S1: K=256 (1 chunk), N=64, out -> sH64
        stage<16, 16,  64, 2, false, true >(smX,  smH64, smW, pbuf, cnext,
                                            b1 + e * 64,  nullptr, nullptr, tid, 0);
        // S2: K=64 (1 chunk), N=256, out -> sH2
        stage< 4,  4, 256, 8, false, true >(smH64, smH2, smW, pbuf, cnext,
                                            b2 + e * 256, nullptr, nullptr, tid, 0);
        // S3: K=256 (2 chunks), N=128, out -> sH3
        stage<16,  8, 128, 4, false, true >(smH2,  smH3, smW, pbuf, cnext,
                                            b3 + e * 128, nullptr, nullptr, tid, 0);
        // S4: K=128 (1 chunk, first half), N=64, out -> sH64
        stage< 8,  8,  64, 2, false, true >(smH3, smH64, smW, pbuf, cnext,
                                            b4 + e * 64,  nullptr, nullptr, tid, 0);
        // S5: K=64 (shares S4's chunk at +16KB), N=128, gated accumulate
        stage< 4,  4, 128, 4, true,  false>(smH64, 0,    smW, pbuf, cnext,
                                            b5 + e * 128, sG + e * TOK, oacc, tid, 16384u);
    }
    CP_WAIT0();

    // ---- write output [64][128] ----
    {
        const int lane = tid & 31, wid = tid >> 5;
        const int wm = wid & 1, wn = wid >> 1;
        const int ri = lane >> 2, c = lane & 3;
        #pragma unroll
        for (int mt = 0; mt < 2; ++mt) {
            int r0 = wm * 32 + mt * 16 + ri;
            #pragma unroll
            for (int t8 = 0; t8 < 4; ++t8) {
                int n0 = wn * 32 + t8 * 8 + 2 * c;
                const float* o = oacc + (mt * 4 + t8) * 4;
                float2 v0; v0.x = o[0]; v0.y = o[1];
                float2 v1; v1.x = o[2]; v1.y = o[3];
                *reinterpret_cast<float2*>(out + (size_t)(b0 + r0) * 128 + n0) = v0;
                *reinterpret_cast<float2*>(out + (size_t)(b0 + r0 + 8) * 128 + n0) = v1;
            }
        }
    }
}

// ---------------- launcher ----------------
extern "C" void kernel_launch(void* const* d_in, const int* in_sizes, int n_in,
                              void* d_out, int out_size)
{
    (void)in_sizes; (void)n_in; (void)out_size;
    const float* x  = (const float*)d_in[0];
    const float* Wg = (const float*)d_in[1];
    const float* bg = (const float*)d_in[2];
    const float* W1 = (const float*)d_in[3];
    const float* b1 = (const float*)d_in[4];
    const float* W2 = (const float*)d_in[5];
    const float* b2 = (const float*)d_in[6];
    const float* W3 = (const float*)d_in[7];
    const float* b3 = (const float*)d_in[8];
    const float* W4 = (const float*)d_in[9];
    const float* b4 = (const float*)d_in[10];
    const float* W5 = (const float*)d_in[11];
    const float* b5 = (const float*)d_in[12];
    float* out = (float*)d_out;

    repack_all<<<(TOTAL_F16 + 255) / 256, 256>>>(W1, W2, W3, W4, W5);

    cudaFuncSetAttribute(moe_f16_kernel,
                         cudaFuncAttributeMaxDynamicSharedMemorySize, SMEM_BYTES);
    moe_f16_kernel<<<NCTA, NTH, SMEM_BYTES>>>(x, Wg, bg, b1, b2, b3, b4, b5, out);
}

// round 6
// speedup vs baseline: 7.8997x; 1.2376x over previous
#include <cuda_runtime.h>
#include <cuda_fp16.h>
#include <cstdint>

#define NTH 256

namespace {
constexpr int E    = 32;
constexpr int TOK  = 128;
constexpr int NCTA = 16384 / TOK;   // 128

// repacked f16 weights: per-expert 81920 halves (40960 b32), 10 chunks of 16KB
constexpr int EXP_B32   = 40960;
constexpr int TOTAL_F16 = E * EXP_B32 * 2;    // 2,621,440
constexpr int CHUNK_F16 = 8192;               // 16KB

// per-expert b32 bases (consumption order)
constexpr int B32_S1  = 0;        // K=256,N=64  : 8192 b32 (2 chunks)
constexpr int B32_S2A = 8192;     // K=64, N=128 : 4096 (1)
constexpr int B32_S2B = 12288;    // K=64, N=128 : 4096 (1)
constexpr int B32_S3  = 16384;    // K=256,N=128 : 16384 (4)
constexpr int B32_S4  = 32768;    // K=128,N=64  : 4096 (1)
constexpr int B32_S5  = 36864;    // K=64, N=128 : 4096 (1)

// smem byte offsets
constexpr int OFF_SX  = 0;         // x A-frag (K16TOT=16): 65536
constexpr int OFF_H2  = 65536;     // h2 A-frag (K16TOT=16): 65536
constexpr int OFF_H3  = 131072;    // h3 A-frag (K16TOT=8): 32768 (also logits tmp)
constexpr int OFF_H64 = 163840;    // h1/h4 A-frag (K16TOT=4): 16384
constexpr int OFF_WB  = 180224;    // weight double buffer: 2 x 16384
constexpr int OFF_G   = 212992;    // gates [E][128] f32: 16384
constexpr int SMEM_BYTES = 229376;

__device__ __align__(16) __half g_Wh[TOTAL_F16];
}

// ---------------- helpers ----------------
__device__ __forceinline__ uint32_t smem_u32(const void* p) {
    uint32_t a;
    asm("{ .reg .u64 t; cvta.to.shared.u64 t, %1; cvt.u32.u64 %0, t; }" : "=r"(a) : "l"(p));
    return a;
}
__device__ __forceinline__ uint32_t packh(float lo, float hi) {
    uint32_t r;
    asm("cvt.rn.f16x2.f32 %0, %1, %2;" : "=r"(r) : "f"(hi), "f"(lo));
    return r;
}
__device__ __forceinline__ void mma16(float* d, const uint32_t* a, uint32_t b0, uint32_t b1) {
    asm volatile("mma.sync.aligned.m16n8k16.row.col.f32.f16.f16.f32 "
        "{%0,%1,%2,%3}, {%4,%5,%6,%7}, {%8,%9}, {%0,%1,%2,%3};"
        : "+f"(d[0]), "+f"(d[1]), "+f"(d[2]), "+f"(d[3])
        : "r"(a[0]), "r"(a[1]), "r"(a[2]), "r"(a[3]), "r"(b0), "r"(b1));
}
__device__ __forceinline__ void lds128(uint32_t* r, uint32_t addr) {
    asm volatile("ld.shared.v4.u32 {%0,%1,%2,%3}, [%4];"
        : "=r"(r[0]), "=r"(r[1]), "=r"(r[2]), "=r"(r[3]) : "r"(addr));
}
__device__ __forceinline__ void sts64(uint32_t addr, uint32_t h0, uint32_t h1) {
    asm volatile("st.shared.v2.u32 [%0], {%1,%2};" :: "r"(addr), "r"(h0), "r"(h1) : "memory");
}
__device__ __forceinline__ void prefetch16k(uint32_t dst, const __half* src, int tid) {
    uint32_t d = dst + (uint32_t)tid * 16u;
    const char* s = reinterpret_cast<const char*>(src) + tid * 16;
    #pragma unroll
    for (int i = 0; i < 4; ++i)
        asm volatile("cp.async.cg.shared.global [%0], [%1], 16;"
                     :: "r"(d + i * 4096u), "l"(s + i * 4096) : "memory");
}
#define CP_COMMIT() asm volatile("cp.async.commit_group;" ::: "memory")
#define CP_WAIT0()  asm volatile("cp.async.wait_group 0;" ::: "memory")

// ---------------- weight repack ----------------
// W[e][k][n] row-major -> B-fragment f16, blocks of NBLK columns.
__device__ __forceinline__ void repack_one(const float* __restrict__ W, int r,
                                           int K, int NSRC, int NBLK, int base_b32) {
    int KN = K * NSRC;
    int e = r / KN, rr = r % KN;
    int k = rr / NSRC, n = rr % NSRC;
    float v = W[r];
    int blk = n / NBLK, nl = n % NBLK;
    int b32 = blk * (K * NBLK / 2)
            + ((k >> 4) * (NBLK >> 4) + (nl >> 4)) * 128
            + ((nl & 7) * 4 + ((k >> 1) & 3)) * 4
            + ((nl >> 3) & 1) * 2 + ((k >> 3) & 1);
    g_Wh[(e * EXP_B32 + base_b32 + b32) * 2 + (k & 1)] = __float2half_rn(v);
}

__global__ void repack_all(const float* __restrict__ W1, const float* __restrict__ W2,
                           const float* __restrict__ W3, const float* __restrict__ W4,
                           const float* __restrict__ W5) {
    int idx = blockIdx.x * blockDim.x + threadIdx.x;
    if      (idx <  524288) repack_one(W1, idx,           256,  64,  64, B32_S1);
    else if (idx < 1048576) repack_one(W2, idx -  524288,  64, 256, 128, B32_S2A);
    else if (idx < 2097152) repack_one(W3, idx - 1048576, 256, 128, 128, B32_S3);
    else if (idx < 2359296) repack_one(W4, idx - 2097152, 128,  64,  64, B32_S4);
    else if (idx < 2621440) repack_one(W5, idx - 2359296,  64, 128, 128, B32_S5);
}

// ---------------- fused stage ----------------
// D[128, NT*32] = A_frag @ B_chunks + bias; relu -> A-frag (STS.64) or gated accumulate.
template<int K16TOT, int K16PC, int NCH, int NT, int K16OUT, bool GATED>
__device__ __forceinline__ void stage(
    uint32_t smA, uint32_t smOut, uint32_t koff_out, uint32_t smW,
    int& pbuf, int& cnext,
    const float* __restrict__ bias,
    const float* __restrict__ gate, float* oacc,
    int tid)
{
    const int lane = tid & 31, wid = tid >> 5;
    const int wm = wid & 1, wn = wid >> 1;
    const int c = lane & 3, ri = lane >> 2;

    float d[4][NT][4];
    #pragma unroll
    for (int mt = 0; mt < 4; ++mt)
        #pragma unroll
        for (int t = 0; t < NT; ++t)
            #pragma unroll
            for (int q = 0; q < 4; ++q) d[mt][t][q] = 0.f;

    #pragma unroll
    for (int ch = 0; ch < NCH; ++ch) {
        CP_WAIT0();
        __syncthreads();
        int noff = cnext * CHUNK_F16;
        if (noff >= TOTAL_F16) noff = 0;
        prefetch16k(smW + (uint32_t)(pbuf ^ 1) * 16384u, g_Wh + noff, tid);
        CP_COMMIT();
        ++cnext;
        const uint32_t Bbase = smW + (uint32_t)pbuf * 16384u;
        #pragma unroll
        for (int kl = 0; kl < K16PC; ++kl) {
            const int k16 = ch * K16PC + kl;
            uint32_t a[4][4];
            #pragma unroll
            for (int mt = 0; mt < 4; ++mt)
                lds128(a[mt], smA + (uint32_t)((((wm * 4 + mt) * K16TOT + k16) * 32 + lane) * 16));
            #pragma unroll
            for (int p = 0; p < NT / 2; ++p) {
                uint32_t b[4];
                lds128(b, Bbase + (uint32_t)(((kl * 2 * NT + wn * (NT / 2) + p) * 32 + lane) * 16));
                #pragma unroll
                for (int mt = 0; mt < 4; ++mt) {
                    mma16(d[mt][2 * p],     a[mt], b[0], b[1]);
                    mma16(d[mt][2 * p + 1], a[mt], b[2], b[3]);
                }
            }
        }
        pbuf ^= 1;
    }

    // epilogue
    #pragma unroll
    for (int mt = 0; mt < 4; ++mt) {
        const int r0 = wm * 64 + mt * 16 + ri;
        #pragma unroll
        for (int t8 = 0; t8 < NT; ++t8) {
            const int n0 = wn * (NT * 8) + t8 * 8 + 2 * c;
            const float bz0 = __ldg(bias + n0), bz1 = __ldg(bias + n0 + 1);
            if (GATED) {
                const float g0 = gate[r0], g1 = gate[r0 + 8];
                float* o = oacc + (mt * NT + t8) * 4;
                o[0] += g0 * (d[mt][t8][0] + bz0);
                o[1] += g0 * (d[mt][t8][1] + bz1);
                o[2] += g1 * (d[mt][t8][2] + bz0);
                o[3] += g1 * (d[mt][t8][3] + bz1);
            } else {
                uint32_t h0 = packh(fmaxf(d[mt][t8][0] + bz0, 0.f),
                                    fmaxf(d[mt][t8][1] + bz1, 0.f));
                uint32_t h1 = packh(fmaxf(d[mt][t8][2] + bz0, 0.f),
                                    fmaxf(d[mt][t8][3] + bz1, 0.f));
                uint32_t dst = smOut
                    + (uint32_t)((((wm * 4 + mt) * K16OUT + koff_out + ((wn * NT + t8) >> 1)) * 32
                                  + lane) * 16)
                    + (uint32_t)((t8 & 1) * 8);
                sts64(dst, h0, h1);
            }
        }
    }
}

// ---------------- main kernel ----------------
__global__ void __launch_bounds__(NTH, 1) moe_f16_kernel(
    const float* __restrict__ x,
    const float* __restrict__ Wg, const float* __restrict__ bg,
    const float* __restrict__ b1, const float* __restrict__ b2,
    const float* __restrict__ b3, const float* __restrict__ b4,
    const float* __restrict__ b5,
    float* __restrict__ out)
{
    extern __shared__ char smem[];
    const uint32_t smb = smem_u32(smem);
    const uint32_t smX = smb + OFF_SX, smH2 = smb + OFF_H2;
    const uint32_t smH3 = smb + OFF_H3, smH64 = smb + OFF_H64;
    const uint32_t smW = smb + OFF_WB;
    float* sWg  = reinterpret_cast<float*>(smem + OFF_WB);
    float* sLog = reinterpret_cast<float*>(smem + OFF_H3);
    float* sG   = reinterpret_cast<float*>(smem + OFF_G);

    const int tid = threadIdx.x;
    const int b0  = blockIdx.x * TOK;

    // ---- x -> A-fragment f16 layout (K16TOT=16, 8 m-tiles) ----
    #pragma unroll
    for (int i = 0; i < 64; ++i) {
        int u = tid + i * NTH;            // b32 unit over 128 tok x 128 k-pairs
        int tok = u >> 7, k2 = u & 127;
        int k = 2 * k2;
        float2 v = *reinterpret_cast<const float2*>(x + (size_t)(b0 + tok) * 256 + k);
        uint32_t h = packh(v.x, v.y);
        uint32_t b32i = (uint32_t)(((tok >> 4) * 16 + (k >> 4)) * 128
                      + ((tok & 7) * 4 + ((k >> 1) & 3)) * 4
                      + ((k >> 3) & 1) * 2 + ((tok >> 3) & 1));
        *reinterpret_cast<uint32_t*>(smem + OFF_SX + b32i * 4) = h;
    }
    // Wg -> smem (32KB over both weight buffers)
    {
        const float4* s4 = reinterpret_cast<const float4*>(Wg);
        float4* d4 = reinterpret_cast<float4*>(smem + OFF_WB);
        #pragma unroll
        for (int i = 0; i < 8; ++i) d4[tid + i * NTH] = s4[tid + i * NTH];
    }
    __syncthreads();

    // ---- gating logits (fp32, x from gmem) ----
    {
        int tok = tid & 127, eg = (tid >> 7) * 16;
        float lg[16];
        #pragma unroll
        for (int j = 0; j < 16; ++j) lg[j] = 0.f;
        const float* xr = x + (size_t)(b0 + tok) * 256;
        #pragma unroll 2
        for (int k = 0; k < 256; ++k) {
            float a = __ldg(xr + k);
            const float* wr = sWg + k * 32 + eg;
            #pragma unroll
            for (int q = 0; q < 4; ++q) {
                float4 w = *reinterpret_cast<const float4*>(wr + 4 * q);
                lg[4*q+0] += a * w.x; lg[4*q+1] += a * w.y;
                lg[4*q+2] += a * w.z; lg[4*q+3] += a * w.w;
            }
        }
        #pragma unroll
        for (int j = 0; j < 16; ++j) sLog[tok * 32 + eg + j] = lg[j] + __ldg(bg + eg + j);
    }
    __syncthreads();
    if (tid < TOK) {
        float lv[32];
        float m = -1e30f;
        #pragma unroll
        for (int e2 = 0; e2 < 32; ++e2) { lv[e2] = sLog[tid * 32 + e2]; m = fmaxf(m, lv[e2]); }
        float s = 0.f;
        #pragma unroll
        for (int e2 = 0; e2 < 32; ++e2) { lv[e2] = expf(lv[e2] - m); s += lv[e2]; }
        float inv = 1.f / s;
        #pragma unroll
        for (int e2 = 0; e2 < 32; ++e2) sG[e2 * TOK + tid] = lv[e2] * inv;
    }
    __syncthreads();

    // ---- expert loop ----
    float oacc[64];
    #pragma unroll
    for (int j = 0; j < 64; ++j) oacc[j] = 0.f;

    int pbuf = 0, cnext = 1;
    prefetch16k(smW, g_Wh, tid);   // expert 0, chunk 0 (S1 part 1)
    CP_COMMIT();

    for (int e = 0; e < E; ++e) {
        // S1: K=256 (2 chunks), N=64 -> sH64
        stage<16, 8, 2, 2, 4, false>(smX,  smH64, 0, smW, pbuf, cnext,
                                     b1 + e * 64, nullptr, nullptr, tid);
        // S2A: K=64, N=128 (cols 0..127 of h2) -> sH2 k16 0..7
        stage< 4, 4, 1, 4, 16, false>(smH64, smH2, 0, smW, pbuf, cnext,
                                      b2 + e * 256, nullptr, nullptr, tid);
        // S2B: K=64, N=128 (cols 128..255) -> sH2 k16 8..15
        stage< 4, 4, 1, 4, 16, false>(smH64, smH2, 8, smW, pbuf, cnext,
                                      b2 + e * 256 + 128, nullptr, nullptr, tid);
        // S3: K=256 (4 chunks), N=128 -> sH3
        stage<16, 4, 4, 4, 8, false>(smH2,  smH3, 0, smW, pbuf, cnext,
                                     b3 + e * 128, nullptr, nullptr, tid);
        // S4: K=128 (1 chunk), N=64 -> sH64
        stage< 8, 8, 1, 2, 4, false>(smH3, smH64, 0, smW, pbuf, cnext,
                                     b4 + e * 64, nullptr, nullptr, tid);
        // S5: K=64 (1 chunk), N=128, gated accumulate
        stage< 4, 4, 1, 4, 0, true >(smH64, 0, 0, smW, pbuf, cnext,
                                     b5 + e * 128, sG + e * TOK, oacc, tid);
    }
    CP_WAIT0();

    // ---- write output [128][128] ----
    {
        const int lane = tid & 31, wid = tid >> 5;
        const int wm = wid & 1, wn = wid >> 1;
        const int ri = lane >> 2, c = lane & 3;
        #pragma unroll
        for (int mt = 0; mt < 4; ++mt) {
            int r0 = wm * 64 + mt * 16 + ri;
            #pragma unroll
            for (int t8 = 0; t8 < 4; ++t8) {
                int n0 = wn * 32 + t8 * 8 + 2 * c;
                const float* o = oacc + (mt * 4 + t8) * 4;
                float2 v0; v0.x = o[0]; v0.y = o[1];
                float2 v1; v1.x = o[2]; v1.y = o[3];
                *reinterpret_cast<float2*>(out + (size_t)(b0 + r0) * 128 + n0) = v0;
                *reinterpret_cast<float2*>(out + (size_t)(b0 + r0 + 8) * 128 + n0) = v1;
            }
        }
    }
}

// ---------------- launcher ----------------
extern "C" void kernel_launch(void* const* d_in, const int* in_sizes, int n_in,
                              void* d_out, int out_size)
{
    (void)in_sizes; (void)n_in; (void)out_size;
    const float* x  = (const float*)d_in[0];
    const float* Wg = (const float*)d_in[1];
    const float* bg = (const float*)d_in[2];
    const float* W1 = (const float*)d_in[3];
    const float* b1 = (const float*)d_in[4];
    const float* W2 = (const float*)d_in[5];
    const float* b2 = (const float*)d_in[6];
    const float* W3 = (const float*)d_in[7];
    const float* b3 = (const float*)d_in[8];
    const float* W4 = (const float*)d_in[9];
    const float* b4 = (const float*)d_in[10];
    const float* W5 = (const float*)d_in[11];
    const float* b5 = (const float*)d_in[12];
    float* out = (float*)d_out;

    repack_all<<<(TOTAL_F16 + 255) / 256, 256>>>(W1, W2, W3, W4, W5);

    cudaFuncSetAttribute(moe_f16_kernel,
                         cudaFuncAttributeMaxDynamicSharedMemorySize, SMEM_BYTES);
    moe_f16_kernel<<<NCTA, NTH, SMEM_BYTES>>>(x, Wg, bg, b1, b2, b3, b4, b5, out);
}

// round 7
// speedup vs baseline: 8.7726x; 1.1105x over previous
#include <cuda_runtime.h>
#include <cuda_fp16.h>
#include <cstdint>

#define NTH 256

namespace {
constexpr int E    = 32;
constexpr int TOK  = 128;
constexpr int NCTA = 16384 / TOK;   // 128

constexpr int EXP_B32   = 40960;              // per-expert b32 count
constexpr int TOTAL_B32 = E * EXP_B32 + 2048; // + B5 block [32 x 128]
constexpr int TOTAL_F16 = TOTAL_B32 * 2;

// per-expert b32 bases (fragment-linear)
constexpr int B32_S1  = 0;        // K=256,N=64
constexpr int B32_S2A = 8192;     // K=64, N=128
constexpr int B32_S2B = 12288;    // K=64, N=128
constexpr int B32_S3  = 16384;    // K=256,N=128
constexpr int B32_S4  = 32768;    // K=128,N=64
constexpr int B32_S5  = 36864;    // K=64, N=128
constexpr int B32_B5  = E * EXP_B32;   // bias-as-GEMM block

// smem byte offsets
constexpr int OFF_SX  = 0;         // x A-frag (K16TOT=16): 65536
constexpr int OFF_H2  = 65536;     // h2 A-frag (K16TOT=16): 65536 (also Wg staging)
constexpr int OFF_H3  = 131072;    // h3 A-frag (K16TOT=8): 32768 (also logits tmp)
constexpr int OFF_H64 = 163840;    // h1/h4 A-frag (K16TOT=4): 16384
constexpr int OFF_G   = 180224;    // gates [E][128] f32: 16384
constexpr int OFF_GF  = 196608;    // gates A-frag f16 (K16TOT=2): 8192
constexpr int SMEM_BYTES = 204800;

__device__ __align__(16) __half g_Wh[TOTAL_F16];
}

// ---------------- helpers ----------------
__device__ __forceinline__ uint32_t smem_u32(const void* p) {
    uint32_t a;
    asm("{ .reg .u64 t; cvta.to.shared.u64 t, %1; cvt.u32.u64 %0, t; }" : "=r"(a) : "l"(p));
    return a;
}
__device__ __forceinline__ uint32_t packh(float lo, float hi) {
    uint32_t r;
    asm("cvt.rn.f16x2.f32 %0, %1, %2;" : "=r"(r) : "f"(hi), "f"(lo));
    return r;
}
__device__ __forceinline__ void mma16(float* d, const uint32_t* a, uint32_t b0, uint32_t b1) {
    asm volatile("mma.sync.aligned.m16n8k16.row.col.f32.f16.f16.f32 "
        "{%0,%1,%2,%3}, {%4,%5,%6,%7}, {%8,%9}, {%0,%1,%2,%3};"
        : "+f"(d[0]), "+f"(d[1]), "+f"(d[2]), "+f"(d[3])
        : "r"(a[0]), "r"(a[1]), "r"(a[2]), "r"(a[3]), "r"(b0), "r"(b1));
}
__device__ __forceinline__ void lds128(uint32_t* r, uint32_t addr) {
    asm volatile("ld.shared.v4.u32 {%0,%1,%2,%3}, [%4];"
        : "=r"(r[0]), "=r"(r[1]), "=r"(r[2]), "=r"(r[3]) : "r"(addr));
}
__device__ __forceinline__ void sts64(uint32_t addr, uint32_t h0, uint32_t h1) {
    asm volatile("st.shared.v2.u32 [%0], {%1,%2};" :: "r"(addr), "r"(h0), "r"(h1) : "memory");
}
__device__ __forceinline__ void ldg128(uint32_t* r, const char* p) {
    uint4 v = __ldg(reinterpret_cast<const uint4*>(p));
    r[0] = v.x; r[1] = v.y; r[2] = v.z; r[3] = v.w;
}

// ---------------- weight repack ----------------
// W[e][k][n] row-major -> B-fragment f16, blocks of NBLK columns, fragment-linear.
__device__ __forceinline__ void repack_one(const float* __restrict__ W, int r,
                                           int K, int NSRC, int NBLK, int base_b32) {
    int KN = K * NSRC;
    int e = r / KN, rr = r % KN;
    int k = rr / NSRC, n = rr % NSRC;
    float v = W[r];
    int blk = n / NBLK, nl = n % NBLK;
    int b32 = blk * (K * NBLK / 2)
            + ((k >> 4) * (NBLK >> 4) + (nl >> 4)) * 128
            + ((nl & 7) * 4 + ((k >> 1) & 3)) * 4
            + ((nl >> 3) & 1) * 2 + ((k >> 3) & 1);
    g_Wh[(e * EXP_B32 + base_b32 + b32) * 2 + (k & 1)] = __float2half_rn(v);
}

__global__ void repack_all(const float* __restrict__ W1, const float* __restrict__ W2,
                           const float* __restrict__ W3, const float* __restrict__ W4,
                           const float* __restrict__ W5, const float* __restrict__ b5) {
    int idx = blockIdx.x * blockDim.x + threadIdx.x;
    if      (idx <  524288) repack_one(W1, idx,           256,  64,  64, B32_S1);
    else if (idx < 1048576) repack_one(W2, idx -  524288,  64, 256, 128, B32_S2A);
    else if (idx < 2097152) repack_one(W3, idx - 1048576, 256, 128, 128, B32_S3);
    else if (idx < 2359296) repack_one(W4, idx - 2097152, 128,  64,  64, B32_S4);
    else if (idx < 2621440) repack_one(W5, idx - 2359296,  64, 128, 128, B32_S5);
    else if (idx < 2625536) repack_one(b5, idx - 2621440,  32, 128, 128, B32_B5);
}

// ---------------- fused stage ----------------
// MODE 0: relu -> A-frag STS ; MODE 1: relu*gate -> A-frag STS ; MODE 2: accumulate into dacc.
template<int K16TOT, int NT, int K16OUT, int MODE>
__device__ __forceinline__ void stage(
    uint32_t smA, uint32_t smOut, uint32_t koff_out,
    const char* __restrict__ gB,         // byte ptr to this stage's B block
    const float* __restrict__ bias,
    const float* __restrict__ gate,
    float* __restrict__ dacc,
    int tid)
{
    const int lane = tid & 31, wid = tid >> 5;
    const int wm = wid & 1, wn = wid >> 1;
    const int c = lane & 3, ri = lane >> 2;
    constexpr int NFR = NT / 2;                 // B LDG.128 per k16 per warp
    constexpr int KLSTRIDE = 2 * NT * 512;      // bytes per k16 in B block

    float dtmp[MODE == 2 ? 1 : 4 * NT * 4];
    float* d = (MODE == 2) ? dacc : dtmp;
    if (MODE != 2) {
        #pragma unroll
        for (int j = 0; j < 4 * NT * 4; ++j) d[j] = 0.f;
    }

    const char* gw = gB + (size_t)((wn * NFR * 32 + lane) * 16);

    uint32_t bq[3][NFR][4];
    #pragma unroll
    for (int i = 0; i < 2 && i < K16TOT; ++i)
        #pragma unroll
        for (int p = 0; p < NFR; ++p)
            ldg128(bq[i][p], gw + i * KLSTRIDE + p * 512);

    #pragma unroll
    for (int k16 = 0; k16 < K16TOT; ++k16) {
        if (k16 + 2 < K16TOT) {
            #pragma unroll
            for (int p = 0; p < NFR; ++p)
                ldg128(bq[(k16 + 2) % 3][p], gw + (k16 + 2) * KLSTRIDE + p * 512);
        }
        uint32_t a[4][4];
        #pragma unroll
        for (int mt = 0; mt < 4; ++mt)
            lds128(a[mt], smA + (uint32_t)((((wm * 4 + mt) * K16TOT + k16) * 32 + lane) * 16));
        #pragma unroll
        for (int p = 0; p < NFR; ++p) {
            const uint32_t* b = bq[k16 % 3][p];
            #pragma unroll
            for (int mt = 0; mt < 4; ++mt) {
                mma16(d + (mt * NT + 2 * p) * 4,     a[mt], b[0], b[1]);
                mma16(d + (mt * NT + 2 * p + 1) * 4, a[mt], b[2], b[3]);
            }
        }
    }

    if (MODE == 2) return;

    // epilogue: bias + relu (+gate), pack f16, store next stage's A-fragments
    #pragma unroll
    for (int mt = 0; mt < 4; ++mt) {
        const int r0 = wm * 64 + mt * 16 + ri;
        float g0 = 1.f, g1 = 1.f;
        if (MODE == 1) { g0 = gate[r0]; g1 = gate[r0 + 8]; }
        #pragma unroll
        for (int t8 = 0; t8 < NT; ++t8) {
            const int n0 = wn * (NT * 8) + t8 * 8 + 2 * c;
            const float bz0 = __ldg(bias + n0), bz1 = __ldg(bias + n0 + 1);
            const float* dd = d + (mt * NT + t8) * 4;
            float v0 = fmaxf(dd[0] + bz0, 0.f), v1 = fmaxf(dd[1] + bz1, 0.f);
            float v2 = fmaxf(dd[2] + bz0, 0.f), v3 = fmaxf(dd[3] + bz1, 0.f);
            if (MODE == 1) { v0 *= g0; v1 *= g0; v2 *= g1; v3 *= g1; }
            uint32_t h0 = packh(v0, v1), h1 = packh(v2, v3);
            uint32_t dst = smOut
                + (uint32_t)((((wm * 4 + mt) * K16OUT + koff_out + ((wn * NT + t8) >> 1)) * 32
                              + lane) * 16)
                + (uint32_t)((t8 & 1) * 8);
            sts64(dst, h0, h1);
        }
    }
}

// ---------------- main kernel ----------------
__global__ void __launch_bounds__(NTH, 1) moe_f16_kernel(
    const float* __restrict__ x,
    const float* __restrict__ Wg, const float* __restrict__ bg,
    const float* __restrict__ b1, const float* __restrict__ b2,
    const float* __restrict__ b3, const float* __restrict__ b4,
    float* __restrict__ out)
{
    extern __shared__ char smem[];
    const uint32_t smb = smem_u32(smem);
    const uint32_t smX = smb + OFF_SX, smH2 = smb + OFF_H2;
    const uint32_t smH3 = smb + OFF_H3, smH64 = smb + OFF_H64;
    const uint32_t smGF = smb + OFF_GF;
    float* sWg  = reinterpret_cast<float*>(smem + OFF_H2);
    float* sLog = reinterpret_cast<float*>(smem + OFF_H3);
    float* sG   = reinterpret_cast<float*>(smem + OFF_G);

    const int tid = threadIdx.x;
    const int b0  = blockIdx.x * TOK;

    // ---- x -> A-fragment f16 layout (K16TOT=16) ----
    #pragma unroll
    for (int i = 0; i < 64; ++i) {
        int u = tid + i * NTH;
        int tok = u >> 7, k2 = u & 127;
        int k = 2 * k2;
        float2 v = *reinterpret_cast<const float2*>(x + (size_t)(b0 + tok) * 256 + k);
        uint32_t h = packh(v.x, v.y);
        uint32_t b32i = (uint32_t)(((tok >> 4) * 16 + (k >> 4)) * 128
                      + ((tok & 7) * 4 + ((k >> 1) & 3)) * 4
                      + ((k >> 3) & 1) * 2 + ((tok >> 3) & 1));
        *reinterpret_cast<uint32_t*>(smem + OFF_SX + b32i * 4) = h;
    }
    // Wg -> smem (32KB, staged in H2 area)
    {
        const float4* s4 = reinterpret_cast<const float4*>(Wg);
        float4* d4 = reinterpret_cast<float4*>(smem + OFF_H2);
        #pragma unroll
        for (int i = 0; i < 8; ++i) d4[tid + i * NTH] = s4[tid + i * NTH];
    }
    __syncthreads();

    // ---- gating logits (fp32, x from gmem) ----
    {
        int tok = tid & 127, eg = (tid >> 7) * 16;
        float lg[16];
        #pragma unroll
        for (int j = 0; j < 16; ++j) lg[j] = 0.f;
        const float* xr = x + (size_t)(b0 + tok) * 256;
        #pragma unroll 2
        for (int k = 0; k < 256; ++k) {
            float a = __ldg(xr + k);
            const float* wr = sWg + k * 32 + eg;
            #pragma unroll
            for (int q = 0; q < 4; ++q) {
                float4 w = *reinterpret_cast<const float4*>(wr + 4 * q);
                lg[4*q+0] += a * w.x; lg[4*q+1] += a * w.y;
                lg[4*q+2] += a * w.z; lg[4*q+3] += a * w.w;
            }
        }
        #pragma unroll
        for (int j = 0; j < 16; ++j) sLog[tok * 32 + eg + j] = lg[j] + __ldg(bg + eg + j);
    }
    __syncthreads();
    // softmax; store f32 gates [e][tok] and f16 gate A-fragments (K=32 -> 2 k16 tiles)
    if (tid < TOK) {
        float lv[32];
        float m = -1e30f;
        #pragma unroll
        for (int e2 = 0; e2 < 32; ++e2) { lv[e2] = sLog[tid * 32 + e2]; m = fmaxf(m, lv[e2]); }
        float s = 0.f;
        #pragma unroll
        for (int e2 = 0; e2 < 32; ++e2) { lv[e2] = expf(lv[e2] - m); s += lv[e2]; }
        float inv = 1.f / s;
        #pragma unroll
        for (int e2 = 0; e2 < 32; ++e2) lv[e2] *= inv;
        #pragma unroll
        for (int e2 = 0; e2 < 32; ++e2) sG[e2 * TOK + tid] = lv[e2];
        const int tok = tid;
        #pragma unroll
        for (int e2 = 0; e2 < 32; e2 += 2) {
            uint32_t h = packh(lv[e2], lv[e2 + 1]);
            uint32_t b32i = (uint32_t)(((tok >> 4) * 2 + (e2 >> 4)) * 128
                          + ((tok & 7) * 4 + ((e2 >> 1) & 3)) * 4
                          + ((e2 >> 3) & 1) * 2 + ((tok >> 3) & 1));
            *reinterpret_cast<uint32_t*>(smem + OFF_GF + b32i * 4) = h;
        }
    }
    __syncthreads();

    // ---- expert loop; persistent output accumulator ----
    float dacc[64];
    #pragma unroll
    for (int j = 0; j < 64; ++j) dacc[j] = 0.f;

    const char* gWh = reinterpret_cast<const char*>(g_Wh);

    for (int e = 0; e < E; ++e) {
        const char* wb = gWh + (size_t)e * (EXP_B32 * 4);
        // S1: K=256, N=64 -> H64
        stage<16, 2, 4, 0>(smX, smH64, 0, wb + B32_S1 * 4,
                           b1 + e * 64, nullptr, nullptr, tid);
        __syncthreads();
        // S2A/S2B: K=64, N=128 each -> H2 (k16 0..7 / 8..15)
        stage< 4, 4, 16, 0>(smH64, smH2, 0, wb + B32_S2A * 4,
                            b2 + e * 256, nullptr, nullptr, tid);
        stage< 4, 4, 16, 0>(smH64, smH2, 8, wb + B32_S2B * 4,
                            b2 + e * 256 + 128, nullptr, nullptr, tid);
        __syncthreads();
        // S3: K=256, N=128 -> H3
        stage<16, 4, 8, 0>(smH2, smH3, 0, wb + B32_S3 * 4,
                           b3 + e * 128, nullptr, nullptr, tid);
        __syncthreads();
        // S4: K=128, N=64 -> H64, relu * gate folded
        stage< 8, 2, 4, 1>(smH3, smH64, 0, wb + B32_S4 * 4,
                           b4 + e * 64, sG + e * TOK, nullptr, tid);
        __syncthreads();
        // S5: K=64, N=128, accumulate into dacc
        stage< 4, 4, 0, 2>(smH64, 0, 0, wb + B32_S5 * 4,
                           nullptr, nullptr, dacc, tid);
        __syncthreads();
    }

    // ---- bias term: dacc += G[128,32] @ B5[32,128] ----
    stage<2, 4, 0, 2>(smGF, 0, 0, gWh + (size_t)B32_B5 * 4,
                      nullptr, nullptr, dacc, tid);

    // ---- write output [128][128] ----
    {
        const int lane = tid & 31, wid = tid >> 5;
        const int wm = wid & 1, wn = wid >> 1;
        const int ri = lane >> 2, c = lane & 3;
        #pragma unroll
        for (int mt = 0; mt < 4; ++mt) {
            int r0 = wm * 64 + mt * 16 + ri;
            #pragma unroll
            for (int t8 = 0; t8 < 4; ++t8) {
                int n0 = wn * 32 + t8 * 8 + 2 * c;
                const float* o = dacc + (mt * 4 + t8) * 4;
                float2 v0; v0.x = o[0]; v0.y = o[1];
                float2 v1; v1.x = o[2]; v1.y = o[3];
                *reinterpret_cast<float2*>(out + (size_t)(b0 + r0) * 128 + n0) = v0;
                *reinterpret_cast<float2*>(out + (size_t)(b0 + r0 + 8) * 128 + n0) = v1;
            }
        }
    }
}

// ---------------- launcher ----------------
extern "C" void kernel_launch(void* const* d_in, const int* in_sizes, int n_in,
                              void* d_out, int out_size)
{
    (void)in_sizes; (void)n_in; (void)out_size;
    const float* x  = (const float*)d_in[0];
    const float* Wg = (const float*)d_in[1];
    const float* bg = (const float*)d_in[2];
    const float* W1 = (const float*)d_in[3];
    const float* b1 = (const float*)d_in[4];
    const float* W2 = (const float*)d_in[5];
    const float* b2 = (const float*)d_in[6];
    const float* W3 = (const float*)d_in[7];
    const float* b3 = (const float*)d_in[8];
    const float* W4 = (const float*)d_in[9];
    const float* b4 = (const float*)d_in[10];
    const float* W5 = (const float*)d_in[11];
    const float* b5 = (const float*)d_in[12];
    float* out = (float*)d_out;

    repack_all<<<(2625536 + 255) / 256, 256>>>(W1, W2, W3, W4, W5, b5);

    cudaFuncSetAttribute(moe_f16_kernel,
                         cudaFuncAttributeMaxDynamicSharedMemorySize, SMEM_BYTES);
    moe_f16_kernel<<<NCTA, NTH, SMEM_BYTES>>>(x, Wg, bg, b1, b2, b3, b4, out);
}